// round 15
// baseline (speedup 1.0000x reference)
#include <cuda_runtime.h>
#include <cuda_fp16.h>
#include <cstdint>

// Problem constants: x (1,64,256,256), W (192,64), bias (192), 8x8 windows of 32x32.
#define NWIN 64
#define TOK  1024
#define C    64
#define WELEMS (TOK*C)          // 65536 floats per window per tensor

// Scratch (device globals — no allocation allowed)
__device__ uint32_t g_qh  [NWIN*WELEMS/2];      // fp16 half2 [w][t][c/2]
__device__ uint32_t g_kh  [NWIN*WELEMS/2];      // fp16 half2
__device__ uint32_t g_vh  [NWIN*WELEMS/2];      // fp16 half2
__device__ uint32_t g_qmh [NWIN*WELEMS/2];      // fp16 half2, x128 scaled
__device__ uint32_t g_kmh [NWIN*WELEMS/2];      // fp16 half2, x128 scaled
__device__ float    g_part[1024*2*96];          // qkv per-block channel sums
__device__ float    g_ar  [NWIN*NWIN];          // x64 prescaled

// ---------------------------------------------------------------------------
// fp16 helpers
// ---------------------------------------------------------------------------
__device__ __forceinline__ uint32_t pack_half2(float lo, float hi) {
    uint32_t r;
    asm("cvt.rn.f16x2.f32 %0, %1, %2;" : "=r"(r) : "f"(hi), "f"(lo));
    return r;   // d.lo = lo, d.hi = hi
}

#define MMA_F16(d, a, b)                                                      \
    asm volatile(                                                             \
        "mma.sync.aligned.m16n8k16.row.col.f32.f16.f16.f32 "                  \
        "{%0,%1,%2,%3}, {%4,%5,%6,%7}, {%8,%9}, {%0,%1,%2,%3};"               \
        : "+f"((d)[0]), "+f"((d)[1]), "+f"((d)[2]), "+f"((d)[3])              \
        : "r"((a)[0]), "r"((a)[1]), "r"((a)[2]), "r"((a)[3]),                 \
          "r"((b)[0]), "r"((b)[1]))

__device__ __forceinline__ uint32_t smem_u32(const void* p) {
    uint32_t a;
    asm("{ .reg .u64 t; cvta.to.shared.u64 t, %1; cvt.u32.u64 %0, t; }"
        : "=r"(a) : "l"(p));
    return a;
}
__device__ __forceinline__ void ldsm_x4(uint32_t* r, uint32_t addr) {
    asm volatile("ldmatrix.sync.aligned.m8n8.x4.shared.b16 {%0,%1,%2,%3}, [%4];"
        : "=r"(r[0]), "=r"(r[1]), "=r"(r[2]), "=r"(r[3]) : "r"(addr));
}
__device__ __forceinline__ void ldsm_x4_trans(uint32_t* r, uint32_t addr) {
    asm volatile("ldmatrix.sync.aligned.m8n8.x4.trans.shared.b16 {%0,%1,%2,%3}, [%4];"
        : "=r"(r[0]), "=r"(r[1]), "=r"(r[2]), "=r"(r[3]) : "r"(addr));
}
__device__ __forceinline__ void cp_async16(uint32_t dst, const void* src) {
    asm volatile("cp.async.cg.shared.global [%0], [%1], 16;" :: "r"(dst), "l"(src));
}
#define CP_COMMIT() asm volatile("cp.async.commit_group;" ::: "memory")
#define CP_WAIT0()  asm volatile("cp.async.wait_group 0;"  ::: "memory")

// ---------------------------------------------------------------------------
// Kernel 1: qkv = gather(x) @ W^T + bias, split-FP16 (~fp32 accurate).
// (unchanged from R14)
// ---------------------------------------------------------------------------
#define QKV_XW 36
#define QKV_WW 36
#define QKV_SG 100
#define QKV_SMEM ((2*128*QKV_XW + 2*96*QKV_WW + 96)*4 + 192*4)   // 65664 B

__global__ __launch_bounds__(256) void qkv_kernel(const float* __restrict__ x,
                                                  const float* __restrict__ W,
                                                  const float* __restrict__ bias)
{
    extern __shared__ uint32_t smw[];
    uint32_t* Xh = smw;                   // [128][36]
    uint32_t* Xl = Xh + 128*QKV_XW;       // [128][36]
    uint32_t* Wh = Xl + 128*QKV_XW;       // [96][36]
    uint32_t* Wl = Wh + 96*QKV_WW;        // [96][36]
    float*    bs = (float*)(Wl + 96*QKV_WW);   // [96]
    float*    red = bs + 96;              // [192]
    float*    Sg = (float*)smw;           // stage [128][100] (union w/ operands)

    const int tt  = blockIdx.x;
    const int jh  = blockIdx.y;
    const int w   = tt >> 3, seg = tt & 7;
    const int wy  = w >> 3,  wx  = w & 7;
    const int t0  = seg * 128;
    const int tid = threadIdx.x;
    const int warp = tid >> 5, lane = tid & 31;
    const int gid  = lane >> 2, tig = lane & 3;
    const int mwarp = warp >> 1;
    const int nwarp = warp & 1;

    __half* Xhh = (__half*)Xh;            // stride 72 halves/row
    __half* Xlh = (__half*)Xl;
    __half* Whh = (__half*)Wh;
    __half* Wlh = (__half*)Wl;

    #pragma unroll
    for (int i = 0; i < 32; i++) {
        int idx = tid + i*256;
        int ch = idx >> 7, tl = idx & 127;
        int t  = t0 + tl;
        float v = x[ch*65536 + (wy*32 + (t>>5))*256 + wx*32 + (t&31)];
        __half h = __float2half_rn(v);
        Xhh[tl*72 + ch] = h;
        Xlh[tl*72 + ch] = __float2half_rn(v - __half2float(h));
    }
    #pragma unroll
    for (int i = 0; i < 24; i++) {
        int idx = tid + i*256;
        int ch = idx & 63, jl = idx >> 6;
        float v = W[(jh*96 + jl)*64 + ch] * 16.f;
        __half h = __float2half_rn(v);
        Whh[jl*72 + ch] = h;
        Wlh[jl*72 + ch] = __float2half_rn(v - __half2float(h));
    }
    if (tid < 96) bs[tid] = bias[jh*96 + tid];
    __syncthreads();

    float acc[2][6][4];
    #pragma unroll
    for (int mt = 0; mt < 2; mt++)
        #pragma unroll
        for (int nt = 0; nt < 6; nt++)
            #pragma unroll
            for (int e = 0; e < 4; e++) acc[mt][nt][e] = 0.f;

    #pragma unroll
    for (int kk = 0; kk < 4; kk++) {
        int kw = kk*8;
        uint32_t ah[2][4], al[2][4];
        #pragma unroll
        for (int mt = 0; mt < 2; mt++) {
            int r = mwarp*32 + mt*16 + gid;
            ah[mt][0] = Xh[ r     *QKV_XW + kw + tig];
            ah[mt][1] = Xh[(r + 8)*QKV_XW + kw + tig];
            ah[mt][2] = Xh[ r     *QKV_XW + kw + 4 + tig];
            ah[mt][3] = Xh[(r + 8)*QKV_XW + kw + 4 + tig];
            al[mt][0] = Xl[ r     *QKV_XW + kw + tig];
            al[mt][1] = Xl[(r + 8)*QKV_XW + kw + tig];
            al[mt][2] = Xl[ r     *QKV_XW + kw + 4 + tig];
            al[mt][3] = Xl[(r + 8)*QKV_XW + kw + 4 + tig];
        }
        #pragma unroll
        for (int nt = 0; nt < 6; nt++) {
            int j = nwarp*48 + nt*8 + gid;
            uint32_t bh[2], bl[2];
            bh[0] = Wh[j*QKV_WW + kw + tig];
            bh[1] = Wh[j*QKV_WW + kw + 4 + tig];
            bl[0] = Wl[j*QKV_WW + kw + tig];
            bl[1] = Wl[j*QKV_WW + kw + 4 + tig];
            MMA_F16(acc[0][nt], ah[0], bh);
            MMA_F16(acc[0][nt], al[0], bh);
            MMA_F16(acc[0][nt], ah[0], bl);
            MMA_F16(acc[1][nt], ah[1], bh);
            MMA_F16(acc[1][nt], al[1], bh);
            MMA_F16(acc[1][nt], ah[1], bl);
        }
    }
    __syncthreads();

    #pragma unroll
    for (int mt = 0; mt < 2; mt++) {
        int r = mwarp*32 + mt*16 + gid;
        #pragma unroll
        for (int nt = 0; nt < 6; nt++) {
            int j = nwarp*48 + nt*8 + 2*tig;
            Sg[ r     *QKV_SG + j    ] = acc[mt][nt][0]*(1.f/16.f) + bs[j];
            Sg[ r     *QKV_SG + j + 1] = acc[mt][nt][1]*(1.f/16.f) + bs[j+1];
            Sg[(r + 8)*QKV_SG + j    ] = acc[mt][nt][2]*(1.f/16.f) + bs[j];
            Sg[(r + 8)*QKV_SG + j + 1] = acc[mt][nt][3]*(1.f/16.f) + bs[j+1];
        }
    }
    __syncthreads();

    #pragma unroll
    for (int p = 0; p < 12; p++) {
        int idx = tid + p*256;
        int t  = idx / 24, f4 = idx % 24;
        float4 v = *(float4*)&Sg[t*QKV_SG + f4*4];
        int jg = jh*96 + f4*4;
        uint32_t* dst = (jg < 64) ? g_qh : (jg < 128) ? g_kh : g_vh;
        int jj = jg & 63;
        uint2 u;
        u.x = pack_half2(v.x, v.y);
        u.y = pack_half2(v.z, v.w);
        *(uint2*)&dst[w*32768 + (t0 + t)*32 + (jj >> 1)] = u;
    }

    if (tid < 192) {
        int half = tid / 96, col = tid - half*96;
        float s = 0.f;
        #pragma unroll 8
        for (int t = half*64; t < half*64 + 64; t++) s += Sg[t*QKV_SG + col];
        red[tid] = s;
    }
    __syncthreads();
    if (tid < 96)
        g_part[(tt*2 + jh)*96 + tid] = red[tid] + red[tid + 96];
}

// ---------------------------------------------------------------------------
// Kernel 2: a_r (unchanged)
// ---------------------------------------------------------------------------
__global__ void ar_kernel()
{
    __shared__ float qs[NWIN*C], ks[NWIN*C];
    const int tid = threadIdx.x;
    for (int e = tid; e < NWIN*C; e += 256) {
        int w = e >> 6, c = e & 63;
        float sq = 0.f, sk = 0.f;
        #pragma unroll
        for (int seg = 0; seg < 8; seg++) {
            int tt = w*8 + seg;
            sq += g_part[(tt*2 + 0)*96 + c];
            sk += (c < 32) ? g_part[(tt*2 + 0)*96 + 64 + c]
                           : g_part[(tt*2 + 1)*96 + (c - 32)];
        }
        qs[e] = sq; ks[e] = sk;
    }
    __syncthreads();
    for (int e = tid; e < NWIN*NWIN; e += 256) {
        int i = e >> 6, j = e & 63;
        float s = 0.f;
        #pragma unroll
        for (int c = 0; c < 64; c++) s += qs[i*64 + c] * ks[j*64 + c];
        g_ar[e] = fmaxf(s, 0.f) * (1.f/16384.f);   // (1/1024^2) * 64
    }
}

// ---------------------------------------------------------------------------
// Kernel 3: mix (unchanged from R14)
// ---------------------------------------------------------------------------
#define MIX_AW 36
#define MIX_BW 68
#define MIX_SW 68
#define MIX_SMEM ((2*64*MIX_AW + 64*MIX_BW)*4)   // 35840 B

__global__ __launch_bounds__(256) void mix_kernel()
{
    extern __shared__ uint32_t smw[];
    uint32_t* Ah = smw;
    uint32_t* Al = Ah + 64*MIX_AW;
    uint32_t* Bs = Al + 64*MIX_AW;
    uint32_t* Sw = smw;

    const int tid = threadIdx.x;
    const int warp = tid >> 5, lane = tid & 31;
    const int gid  = lane >> 2, tig = lane & 3;
    const int mwarp = warp >> 1;
    const int nwarp = warp & 1;
    const int l8 = lane & 7, lhi = (lane >> 3) & 1, lcol = lane >> 4;
    const uint2* srch = (const uint2*)(blockIdx.y ? g_kh : g_qh);
    uint32_t*    dst  = blockIdx.y ? g_kmh : g_qmh;
    const int pos0 = blockIdx.x * 128;

    #pragma unroll
    for (int p = 0; p < 8; p++) {
        int idx = tid + p*256;
        int i = idx >> 5, jw = idx & 31;
        float v0 = g_ar[i*64 + jw*2], v1 = g_ar[i*64 + jw*2 + 1];
        float h0 = __half2float(__float2half_rn(v0));
        float h1 = __half2float(__float2half_rn(v1));
        Ah[i*MIX_AW + jw] = pack_half2(v0, v1);
        Al[i*MIX_AW + jw] = pack_half2(v0 - h0, v1 - h1);
    }
    #pragma unroll
    for (int p = 0; p < 8; p++) {
        int idx = tid + p*256;
        int j = idx >> 5, u2 = idx & 31;
        uint2 u = srch[j*16384 + (pos0 >> 2) + u2];
        *(uint2*)&Bs[j*MIX_BW + u2*2] = u;
    }
    __syncthreads();

    float acc[8][4];
    #pragma unroll
    for (int nt = 0; nt < 8; nt++)
        #pragma unroll
        for (int e = 0; e < 4; e++) acc[nt][e] = 0.f;

    const uint32_t bbase = smem_u32(Bs);
    const int r = mwarp*16 + gid;

    #pragma unroll
    for (int kk = 0; kk < 4; kk++) {
        uint32_t ah[4], al[4];
        ah[0] = Ah[ r     *MIX_AW + kk*8 + tig];
        ah[1] = Ah[(r + 8)*MIX_AW + kk*8 + tig];
        ah[2] = Ah[ r     *MIX_AW + kk*8 + 4 + tig];
        ah[3] = Ah[(r + 8)*MIX_AW + kk*8 + 4 + tig];
        al[0] = Al[ r     *MIX_AW + kk*8 + tig];
        al[1] = Al[(r + 8)*MIX_AW + kk*8 + tig];
        al[2] = Al[ r     *MIX_AW + kk*8 + 4 + tig];
        al[3] = Al[(r + 8)*MIX_AW + kk*8 + 4 + tig];
        #pragma unroll
        for (int ntv = 0; ntv < 4; ntv++) {
            int n0 = nwarp*64 + ntv*16;
            uint32_t b[4];
            ldsm_x4_trans(b, bbase + (uint32_t)((kk*16 + l8 + lhi*8)*(MIX_BW*4)
                                                + (n0 + lcol*8)*2));
            uint32_t b01[2] = {b[0], b[1]}, b23[2] = {b[2], b[3]};
            MMA_F16(acc[2*ntv],     ah, b01);
            MMA_F16(acc[2*ntv],     al, b01);
            MMA_F16(acc[2*ntv + 1], ah, b23);
            MMA_F16(acc[2*ntv + 1], al, b23);
        }
    }
    __syncthreads();

    #pragma unroll
    for (int nt = 0; nt < 8; nt++) {
        int wc = nwarp*32 + nt*4 + tig;
        Sw[ r     *MIX_SW + wc] = pack_half2(acc[nt][0]*2.f, acc[nt][1]*2.f);
        Sw[(r + 8)*MIX_SW + wc] = pack_half2(acc[nt][2]*2.f, acc[nt][3]*2.f);
    }
    __syncthreads();

    #pragma unroll
    for (int p = 0; p < 4; p++) {
        int idx = tid + p*256;
        int i = idx >> 4, w4 = idx & 15;
        uint4 v = *(uint4*)&Sw[i*MIX_SW + w4*4];
        ((uint4*)dst)[i*8192 + (pos0 >> 3) + w4] = v;
    }
}

// ---------------------------------------------------------------------------
// Kernel 4 (dominant): O = relu(Qm Km^T) V, fp16 mma, register-resident S.
// R15: 64-row s-chunks -> sacc/ap halve, smem 55 KB -> 3 CTAs/SM (12 warps),
// K b-frags shared across both m-tiles in MMA1. Accumulation order over k is
// identical to R14 (bit-identical output). 16 chunks, 1 barrier each.
// ---------------------------------------------------------------------------
#define AT_SG 68                     // output stage stride (floats)
#define AT_TQ  (128*144)             // Q tile bytes (18432)
#define AT_TKV (64*144)              // K/V chunk bytes (9216)
#define ATTN_SMEM (AT_TQ + 4*AT_TKV) // 55296 B

__global__ __launch_bounds__(128, 3) void attn_kernel(float* __restrict__ out)
{
    extern __shared__ uint32_t smw[];
    float* Sg = (float*)smw;             // output stage (reuses Q region)

    const int bx = blockIdx.x;
    const int w  = bx >> 3, seg = bx & 7;
    const int wy = w >> 3,  wx  = w & 7;
    const int t0 = seg * 128;
    const int tid = threadIdx.x;
    const int warp = tid >> 5, lane = tid & 31;
    const int gid = lane >> 2, tig = lane & 3;
    const int l8 = lane & 7, lhi = (lane >> 3) & 1, lcol = lane >> 4;

    const uint32_t sb = smem_u32(smw);
    const char* qsrc = (const char*)g_qmh + w*131072;
    const char* ksrc = (const char*)g_kmh + w*131072;
    const char* vsrc = (const char*)g_vh  + w*131072;

    // Prologue: Q tile (8 slots/thr) + chunk-0 K/V (4 slots each/thr)
    #pragma unroll
    for (int p = 0; p < 8; p++) {
        int slot = tid + p*128;          // 1024 slots = 128 rows x 8 segs
        int row = slot >> 3, sg16 = slot & 7;
        cp_async16(sb + row*144 + sg16*16, qsrc + (t0 + row)*128 + sg16*16);
    }
    #pragma unroll
    for (int p = 0; p < 4; p++) {
        int slot = tid + p*128;          // 512 slots = 64 rows x 8 segs
        int row = slot >> 3, sg16 = slot & 7;
        cp_async16(sb + AT_TQ             + row*144 + sg16*16, ksrc + row*128 + sg16*16);
        cp_async16(sb + AT_TQ + 2*AT_TKV  + row*144 + sg16*16, vsrc + row*128 + sg16*16);
    }
    CP_COMMIT();

    float oacc[2][8][4];
    #pragma unroll
    for (int mt = 0; mt < 2; mt++)
        #pragma unroll
        for (int nt = 0; nt < 8; nt++)
            #pragma unroll
            for (int e = 0; e < 4; e++) oacc[mt][nt][e] = 0.f;

    #pragma unroll 1
    for (int chunk = 0; chunk < 16; chunk++) {
        CP_WAIT0();
        __syncthreads();                 // buf[chunk&1] ready for all warps

        // Issue next chunk's K/V into the other buffer (hidden under MMAs)
        if (chunk < 15) {
            const int sn = (chunk + 1) * 64;
            const uint32_t kb_n = sb + AT_TQ            + ((chunk + 1) & 1)*AT_TKV;
            const uint32_t vb_n = sb + AT_TQ + 2*AT_TKV + ((chunk + 1) & 1)*AT_TKV;
            #pragma unroll
            for (int p = 0; p < 4; p++) {
                int slot = tid + p*128;
                int row = slot >> 3, sg16 = slot & 7;
                cp_async16(kb_n + row*144 + sg16*16, ksrc + (sn + row)*128 + sg16*16);
                cp_async16(vb_n + row*144 + sg16*16, vsrc + (sn + row)*128 + sg16*16);
            }
            CP_COMMIT();
        }

        const uint32_t kb = sb + AT_TQ            + (chunk & 1)*AT_TKV;
        const uint32_t vb = sb + AT_TQ + 2*AT_TKV + (chunk & 1)*AT_TKV;

        // ---- MMA1: S'(32x64) per warp; K b-frags shared across both m-tiles
        float sacc[2][8][4];
        #pragma unroll
        for (int mt = 0; mt < 2; mt++)
            #pragma unroll
            for (int nt = 0; nt < 8; nt++)
                #pragma unroll
                for (int e = 0; e < 4; e++) sacc[mt][nt][e] = 0.f;

        #pragma unroll
        for (int kk = 0; kk < 4; kk++) {
            uint32_t a0[4], a1[4];
            ldsm_x4(a0, sb + (uint32_t)((warp*32      + l8 + lhi*8)*144 + kk*32 + lcol*16));
            ldsm_x4(a1, sb + (uint32_t)((warp*32 + 16 + l8 + lhi*8)*144 + kk*32 + lcol*16));
            #pragma unroll
            for (int nt2 = 0; nt2 < 4; nt2++) {
                uint32_t b[4];
                ldsm_x4(b, kb + (uint32_t)((nt2*16 + l8 + lhi*8)*144 + kk*32 + lcol*16));
                uint32_t b02[2] = {b[0], b[2]}, b13[2] = {b[1], b[3]};
                MMA_F16(sacc[0][2*nt2],     a0, b02);
                MMA_F16(sacc[0][2*nt2 + 1], a0, b13);
                MMA_F16(sacc[1][2*nt2],     a1, b02);
                MMA_F16(sacc[1][2*nt2 + 1], a1, b13);
            }
        }

        // relu + pack: MMA1 c-frags -> MMA2 a-frags (register-resident S)
        uint32_t ap[2][4][4];
        #pragma unroll
        for (int mt = 0; mt < 2; mt++)
            #pragma unroll
            for (int kk2 = 0; kk2 < 4; kk2++) {
                ap[mt][kk2][0] = pack_half2(fmaxf(sacc[mt][2*kk2][0], 0.f),
                                            fmaxf(sacc[mt][2*kk2][1], 0.f));
                ap[mt][kk2][1] = pack_half2(fmaxf(sacc[mt][2*kk2][2], 0.f),
                                            fmaxf(sacc[mt][2*kk2][3], 0.f));
                ap[mt][kk2][2] = pack_half2(fmaxf(sacc[mt][2*kk2+1][0], 0.f),
                                            fmaxf(sacc[mt][2*kk2+1][1], 0.f));
                ap[mt][kk2][3] = pack_half2(fmaxf(sacc[mt][2*kk2+1][2], 0.f),
                                            fmaxf(sacc[mt][2*kk2+1][3], 0.f));
            }

        // ---- MMA2: O(32x64) += S' V, V fragments shared across both m-tiles
        #pragma unroll
        for (int kk2 = 0; kk2 < 4; kk2++) {
            #pragma unroll
            for (int ntv = 0; ntv < 4; ntv++) {
                uint32_t b[4];
                ldsm_x4_trans(b, vb + (uint32_t)((kk2*16 + l8 + lhi*8)*144
                                                 + (ntv*16 + lcol*8)*2));
                uint32_t b01[2] = {b[0], b[1]}, b23[2] = {b[2], b[3]};
                MMA_F16(oacc[0][2*ntv],     ap[0][kk2], b01);
                MMA_F16(oacc[0][2*ntv + 1], ap[0][kk2], b23);
                MMA_F16(oacc[1][2*ntv],     ap[1][kk2], b01);
                MMA_F16(oacc[1][2*ntv + 1], ap[1][kk2], b23);
            }
        }
    }

    __syncthreads();
    // stage O/16384 as fp32 [t][c] (reuses Q region: 34.8 KB < 55.3 KB)
    #pragma unroll
    for (int mt = 0; mt < 2; mt++) {
        const int r0w = warp*32 + mt*16;
        #pragma unroll
        for (int nt = 0; nt < 8; nt++) {
            int c = nt*8 + 2*tig;
            Sg[(r0w + gid    )*AT_SG + c    ] = oacc[mt][nt][0] * (1.f/16384.f);
            Sg[(r0w + gid    )*AT_SG + c + 1] = oacc[mt][nt][1] * (1.f/16384.f);
            Sg[(r0w + gid + 8)*AT_SG + c    ] = oacc[mt][nt][2] * (1.f/16384.f);
            Sg[(r0w + gid + 8)*AT_SG + c + 1] = oacc[mt][nt][3] * (1.f/16384.f);
        }
    }
    __syncthreads();

    #pragma unroll
    for (int i = 0; i < 64; i++) {
        int idx = tid + i*128;
        int ch = idx >> 7, tl = idx & 127;
        int t  = t0 + tl;
        out[ch*65536 + (wy*32 + (t>>5))*256 + wx*32 + (t&31)] = Sg[tl*AT_SG + ch];
    }
}

// ---------------------------------------------------------------------------
extern "C" void kernel_launch(void* const* d_in, const int* in_sizes, int n_in,
                              void* d_out, int out_size)
{
    const float* x    = (const float*)d_in[0];
    const float* W    = (const float*)d_in[1];
    const float* bias = (const float*)d_in[2];
    float* out = (float*)d_out;

    cudaFuncSetAttribute(qkv_kernel,  cudaFuncAttributeMaxDynamicSharedMemorySize, QKV_SMEM);
    cudaFuncSetAttribute(mix_kernel,  cudaFuncAttributeMaxDynamicSharedMemorySize, MIX_SMEM);
    cudaFuncSetAttribute(attn_kernel, cudaFuncAttributeMaxDynamicSharedMemorySize, ATTN_SMEM);

    qkv_kernel <<<dim3(512, 2), 256, QKV_SMEM>>>(x, W, bias);
    ar_kernel  <<<1,            256>>>();
    mix_kernel <<<dim3(512, 2), 256, MIX_SMEM>>>();
    attn_kernel<<<512,          128, ATTN_SMEM>>>(out);
}